// round 3
// baseline (speedup 1.0000x reference)
#include <cuda_runtime.h>
#include <math.h>

#define B_ 256
typedef unsigned long long u64;

// ---------------- device scratch ----------------
__device__ float g_Weff[25 * 220];
__device__ float g_beff[25];
__device__ float g_y1[B_ * 25 * 330];
__device__ float g_y2[B_ * 50 * 107];
__device__ float g_y3[B_ * 100 * 32];
__device__ float g_feat[B_ * 1400];

__device__ __forceinline__ float elu1(float x) { return x > 0.f ? x : expm1f(x); }

__device__ __forceinline__ u64 pk2(float lo, float hi) {
    u64 r; asm("mov.b64 %0, {%1, %2};" : "=l"(r) : "f"(lo), "f"(hi)); return r;
}
__device__ __forceinline__ float2 up2(u64 a) {
    float2 r; asm("mov.b64 {%0, %1}, %2;" : "=f"(r.x), "=f"(r.y) : "l"(a)); return r;
}
__device__ __forceinline__ void fma2(u64& a, u64 x, u64 w) {
    asm("fma.rn.f32x2 %0, %1, %2, %0;" : "+l"(a) : "l"(x), "l"(w));
}

// ---------------- kernel 0: fold conv_time into conv_spat ----------------
__global__ void precompute_k(const float* __restrict__ w_time, const float* __restrict__ b_time,
                             const float* __restrict__ w_spat, const float* __restrict__ b_spat)
{
    for (int idx = threadIdx.x; idx < 25 * 220; idx += blockDim.x) {
        int p = idx / 220, rem = idx % 220, c = rem / 10, k = rem % 10;
        float s = 0.f;
        #pragma unroll
        for (int o = 0; o < 25; o++)
            s = fmaf(w_spat[p * 550 + o * 22 + c], w_time[o * 10 + k], s);
        g_Weff[idx] = s;
    }
    if (threadIdx.x < 25) {
        int p = threadIdx.x;
        float s = b_spat[p];
        for (int o = 0; o < 25; o++) {
            float w = 0.f;
            for (int c = 0; c < 22; c++) w += w_spat[p * 550 + o * 22 + c];
            s = fmaf(b_time[o], w, s);
        }
        g_beff[p] = s;
    }
}

// ---------------- position-paired conv body: 6 conv positions / thread ----------
// acc[p][j] holds conv positions (2j, 2j+1) packed. xs pre-offset by 6*tq (8B aligned).
template<int P, int C, int XS, int WS>
__device__ __forceinline__ void conv6(const float* __restrict__ xs,
                                      const float* __restrict__ ws,
                                      u64 (&acc)[P][3])
{
    #pragma unroll
    for (int p = 0; p < P; p++)
        #pragma unroll
        for (int j = 0; j < 3; j++) acc[p][j] = 0ull;
    #pragma unroll 1
    for (int c = 0; c < C; c++) {
        const float* xr = xs + c * XS;
        u64 pe[8]; float2 f[8];
        #pragma unroll
        for (int i = 0; i < 7; i++) { pe[i] = reinterpret_cast<const u64*>(xr)[i]; f[i] = up2(pe[i]); }
        float s14 = xr[14];
        u64 po[7];
        #pragma unroll
        for (int i = 0; i < 6; i++) po[i] = pk2(f[i].y, f[i + 1].x);
        po[6] = pk2(f[6].y, s14);
        #pragma unroll
        for (int p = 0; p < P; p++) {
            const float* wp = ws + p * WS + c * 12;
            float4 w0 = *reinterpret_cast<const float4*>(wp);
            float4 w1 = *reinterpret_cast<const float4*>(wp + 4);
            float2 w2 = *reinterpret_cast<const float2*>(wp + 8);
            float wk[10] = {w0.x, w0.y, w0.z, w0.w, w1.x, w1.y, w1.z, w1.w, w2.x, w2.y};
            #pragma unroll
            for (int k = 0; k < 10; k++) {
                u64 wpr = pk2(wk[k], wk[k]);
                fma2(acc[p][0], (k & 1)       ? po[k >> 1]       : pe[k >> 1],       wpr);
                fma2(acc[p][1], ((k + 2) & 1) ? po[(k + 2) >> 1] : pe[(k + 2) >> 1], wpr);
                fma2(acc[p][2], ((k + 4) & 1) ? po[(k + 4) >> 1] : pe[(k + 4) >> 1], wpr);
            }
        }
    }
}

template<int P>
__device__ __forceinline__ void store6(u64 (&acc)[P][3], const float* __restrict__ bias,
                                       float* __restrict__ dst, int ldc, int P0, int tp0,
                                       bool second_valid)
{
    #pragma unroll
    for (int p = 0; p < P; p++) {
        float2 a0 = up2(acc[p][0]), a1 = up2(acc[p][1]), a2 = up2(acc[p][2]);
        float bv = bias[P0 + p];
        float m0 = fmaxf(a0.x, fmaxf(a0.y, a1.x)) + bv;
        dst[(P0 + p) * ldc + tp0] = elu1(m0);
        if (second_valid) {
            float m1 = fmaxf(a1.y, fmaxf(a2.x, a2.y)) + bv;
            dst[(P0 + p) * ldc + tp0 + 1] = elu1(m1);
        }
    }
}

// sample-paired body (stage 3): acc[p][j] = (sampleA pos j, sampleB pos j)
template<int P, int C, int XS, int WS>
__device__ __forceinline__ void conv3x2(const float* __restrict__ x0,
                                        const float* __restrict__ x1,
                                        const float* __restrict__ ws,
                                        u64 (&acc)[P][3])
{
    #pragma unroll
    for (int p = 0; p < P; p++)
        #pragma unroll
        for (int j = 0; j < 3; j++) acc[p][j] = 0ull;
    #pragma unroll 1
    for (int c = 0; c < C; c++) {
        u64 xp[12];
        #pragma unroll
        for (int i = 0; i < 12; i++) xp[i] = pk2(x0[c * XS + i], x1[c * XS + i]);
        #pragma unroll
        for (int p = 0; p < P; p++) {
            const float* wp = ws + p * WS + c * 12;
            float4 w0 = *reinterpret_cast<const float4*>(wp);
            float4 w1 = *reinterpret_cast<const float4*>(wp + 4);
            float2 w2 = *reinterpret_cast<const float2*>(wp + 8);
            float wk[10] = {w0.x, w0.y, w0.z, w0.w, w1.x, w1.y, w1.z, w1.w, w2.x, w2.y};
            #pragma unroll
            for (int k = 0; k < 10; k++) {
                u64 wpr = pk2(wk[k], wk[k]);
                fma2(acc[p][0], xp[k + 0], wpr);
                fma2(acc[p][1], xp[k + 1], wpr);
                fma2(acc[p][2], xp[k + 2], wpr);
            }
        }
    }
}

// ---------------- stage 1: x[256,22,1000] -> y1[256,25,330] ----------------
// grid (256, 3 time-thirds); block 224 = 56 tq x 4 pgroups; smem 56,672 B
__global__ __launch_bounds__(224, 2) void stage1_k(const float* __restrict__ x)
{
    extern __shared__ float sm[];
    float* xs = sm;                 // [22][344]
    float* ws = sm + 22 * 344;      // [25][264]
    __shared__ float bs[25];
    const int b = blockIdx.x, third = blockIdx.y;
    const int base = third * 330;
    const float* xb = x + b * 22000;
    for (int i = threadIdx.x; i < 22 * 339; i += 224) {
        int c = i / 339, t = i - c * 339;
        xs[c * 344 + t] = xb[c * 1000 + base + t];
    }
    for (int i = threadIdx.x; i < 5500; i += 224) {
        int p = i / 220, r = i - p * 220, c = r / 10, k = r - c * 10;
        ws[p * 264 + c * 12 + k] = g_Weff[i];
    }
    if (threadIdx.x < 25) bs[threadIdx.x] = g_beff[threadIdx.x];
    __syncthreads();

    const int tq = threadIdx.x % 56, pg = threadIdx.x / 56;
    if (tq >= 55) return;
    const float* xp = xs + 6 * tq;
    const int tp0 = third * 110 + 2 * tq;
    float* dst = g_y1 + b * 8250;

    if (pg == 0) {
        u64 acc[7][3]; conv6<7, 22, 344, 264>(xp, ws, acc);
        store6<7>(acc, bs, dst, 330, 0, tp0, true);
    } else {
        const int P0 = 7 + 6 * (pg - 1);
        u64 acc[6][3]; conv6<6, 22, 344, 264>(xp, ws + P0 * 264, acc);
        store6<6>(acc, bs, dst, 330, P0, tp0, true);
    }
}

// ---------------- stage 2: y1 -> y2[256,50,107] ----------------
// grid (256, 2 channel-halves); block 224 = 56 tq x 4 pg; smem 63,600 B
__global__ __launch_bounds__(224, 2) void stage2_k(const float* __restrict__ w2,
                                                   const float* __restrict__ b2)
{
    extern __shared__ float sm[];
    float* xs = sm;                 // [25][336] zero-padded
    float* ws = sm + 25 * 336;      // [25][300]
    const int b = blockIdx.x, half = blockIdx.y;
    const float* xb = g_y1 + b * 8250;
    for (int i = threadIdx.x; i < 25 * 336; i += 224) {
        int c = i / 336, t = i - c * 336;
        xs[i] = (t < 330) ? xb[c * 330 + t] : 0.f;
    }
    for (int i = threadIdx.x; i < 6250; i += 224) {
        int p = i / 250, r = i - p * 250, c = r / 10, k = r - c * 10;
        ws[p * 300 + c * 12 + k] = w2[(half * 25 + p) * 250 + r];
    }
    __syncthreads();

    const int tq = threadIdx.x % 56, pg = threadIdx.x / 56;
    if (tq >= 54) return;
    const float* xp = xs + 6 * tq;
    const int tp0 = 2 * tq;
    const bool sv = (tq < 53);
    float* dst = g_y2 + b * 5350 + half * 25 * 107;
    const float* bias = b2 + half * 25;

    if (pg == 0) {
        u64 acc[7][3]; conv6<7, 25, 336, 300>(xp, ws, acc);
        store6<7>(acc, bias, dst, 107, 0, tp0, sv);
    } else {
        const int P0 = 7 + 6 * (pg - 1);
        u64 acc[6][3]; conv6<6, 25, 336, 300>(xp, ws + P0 * 300, acc);
        store6<6>(acc, bias, dst, 107, P0, tp0, sv);
    }
}

// ---------------- stage 3: y2 -> y3[256,100,32] (sample-paired) ----------------
// grid (128 pairs, 4 channel-quarters); block 256 = 32 tp x 8 g; smem 103,200 B
__global__ __launch_bounds__(256, 2) void stage3_k(const float* __restrict__ w3,
                                                   const float* __restrict__ b3)
{
    extern __shared__ float sm[];
    float* xs = sm;                 // [2][50][108]
    float* ws = sm + 10800;         // [25][600]
    const int sp = blockIdx.x, cg = blockIdx.y;
    const int s0 = sp * 2;
    for (int i = threadIdx.x; i < 10800; i += 256) {
        int s = i / 5400, r = i - s * 5400, c = r / 108, t = r - c * 108;
        xs[i] = (t < 107) ? g_y2[(s0 + s) * 5350 + c * 107 + t] : 0.f;
    }
    for (int i = threadIdx.x; i < 12500; i += 256) {
        int p = i / 500, r = i - p * 500, c = r / 10, k = r - c * 10;
        ws[p * 600 + c * 12 + k] = w3[(cg * 25 + p) * 500 + r];
    }
    __syncthreads();

    const int tp = threadIdx.x & 31;
    const int g  = threadIdx.x >> 5;
    const float* x0 = xs + 3 * tp;
    const float* x1 = xs + 5400 + 3 * tp;
    const int P0 = (g == 0) ? 0 : 4 + 3 * (g - 1);

    u64 acc4[4][3];
    if (g == 0) {
        conv3x2<4, 50, 108, 600>(x0, x1, ws, acc4);
        #pragma unroll
        for (int p = 0; p < 4; p++) {
            int og = cg * 25 + p;
            float bv = __ldg(&b3[og]);
            float2 a0 = up2(acc4[p][0]), a1 = up2(acc4[p][1]), a2 = up2(acc4[p][2]);
            g_y3[s0 * 3200 + og * 32 + tp]       = elu1(fmaxf(a0.x, fmaxf(a1.x, a2.x)) + bv);
            g_y3[(s0 + 1) * 3200 + og * 32 + tp] = elu1(fmaxf(a0.y, fmaxf(a1.y, a2.y)) + bv);
        }
    } else {
        u64 acc[3][3];
        conv3x2<3, 50, 108, 600>(x0, x1, ws + P0 * 600, acc);
        #pragma unroll
        for (int p = 0; p < 3; p++) {
            int og = cg * 25 + P0 + p;
            float bv = __ldg(&b3[og]);
            float2 a0 = up2(acc[p][0]), a1 = up2(acc[p][1]), a2 = up2(acc[p][2]);
            g_y3[s0 * 3200 + og * 32 + tp]       = elu1(fmaxf(a0.x, fmaxf(a1.x, a2.x)) + bv);
            g_y3[(s0 + 1) * 3200 + og * 32 + tp] = elu1(fmaxf(a0.y, fmaxf(a1.y, a2.y)) + bv);
        }
    }
}

// ---------------- stage 4: y3 -> feat[256,1400] ----------------
// thread-per-output-channel; 21 conv positions = 10 pairs + 1 scalar; smem 53,008 B
__global__ __launch_bounds__(224, 2) void stage4_k(const float* __restrict__ w4,
                                                   const float* __restrict__ b4)
{
    extern __shared__ float sm[];
    float* xs = sm;             // [100][32]
    float* wc = sm + 3200;      // [50][201]
    const int b = blockIdx.x;
    const int o = threadIdx.x;
    for (int i = threadIdx.x; i < 3200; i += 224) xs[i] = g_y3[b * 3200 + i];

    u64 acc[10];
    float acc20 = 0.f;
    #pragma unroll
    for (int i = 0; i < 10; i++) acc[i] = 0ull;

    for (int c0 = 0; c0 < 100; c0 += 5) {
        __syncthreads();
        const float2* wg = reinterpret_cast<const float2*>(w4 + c0 * 10);
        for (int i = threadIdx.x; i < 5000; i += 224) {
            int oo = i / 25, r2 = i - oo * 25;
            float2 v = __ldg(&wg[oo * 500 + r2]);
            wc[(2 * r2) * 201 + oo]     = v.x;
            wc[(2 * r2 + 1) * 201 + oo] = v.y;
        }
        __syncthreads();
        if (o < 200) {
            #pragma unroll
            for (int c = 0; c < 5; c++) {
                const float* xr = xs + (c0 + c) * 32;
                u64 pe[16]; float2 f[16];
                #pragma unroll
                for (int i = 0; i < 16; i++) { pe[i] = reinterpret_cast<const u64*>(xr)[i]; f[i] = up2(pe[i]); }
                u64 po[15];
                #pragma unroll
                for (int i = 0; i < 15; i++) po[i] = pk2(f[i].y, f[i + 1].x);
                #pragma unroll
                for (int k = 0; k < 10; k++) {
                    float wv = wc[(c * 10 + k) * 201 + o];
                    u64 wpr = pk2(wv, wv);
                    #pragma unroll
                    for (int j = 0; j < 10; j++) {
                        int m = 2 * j + k;
                        fma2(acc[j], (m & 1) ? po[m >> 1] : pe[m >> 1], wpr);
                    }
                    acc20 = fmaf(wv, f[(20 + k) >> 1].x * 0.f + ((20 + k) & 1 ? f[(20 + k) >> 1].y : f[(20 + k) >> 1].x), acc20);
                }
            }
        }
    }

    if (o < 200) {
        float pv[21];
        #pragma unroll
        for (int j = 0; j < 10; j++) { float2 a = up2(acc[j]); pv[2 * j] = a.x; pv[2 * j + 1] = a.y; }
        pv[20] = acc20;
        float bo = __ldg(&b4[o]);
        #pragma unroll
        for (int t = 0; t < 7; t++) {
            float m = fmaxf(pv[3 * t], fmaxf(pv[3 * t + 1], pv[3 * t + 2])) + bo;
            g_feat[b * 1400 + o * 7 + t] = elu1(m);
        }
    }
}

// ---------------- head ----------------
__global__ void head_k(const int* __restrict__ sid, const float* __restrict__ hW,
                       const float* __restrict__ hB, float* __restrict__ out)
{
    const int b = blockIdx.x;
    const int s = sid[b];
    const float* f = g_feat + b * 1400;
    const float* W = hW + s * (4 * 1400);
    float acc[4] = {0.f, 0.f, 0.f, 0.f};
    for (int i = threadIdx.x; i < 1400; i += blockDim.x) {
        float fv = f[i];
        #pragma unroll
        for (int o = 0; o < 4; o++) acc[o] = fmaf(fv, __ldg(&W[o * 1400 + i]), acc[o]);
    }
    #pragma unroll
    for (int off = 16; off > 0; off >>= 1) {
        #pragma unroll
        for (int o = 0; o < 4; o++) acc[o] += __shfl_down_sync(0xFFFFFFFFu, acc[o], off);
    }
    __shared__ float red[4][4];
    const int w = threadIdx.x >> 5, l = threadIdx.x & 31;
    if (l == 0) {
        #pragma unroll
        for (int o = 0; o < 4; o++) red[o][w] = acc[o];
    }
    __syncthreads();
    if (threadIdx.x < 4) {
        int o = threadIdx.x;
        out[b * 4 + o] = red[o][0] + red[o][1] + red[o][2] + red[o][3] + __ldg(&hB[s * 4 + o]);
    }
}

// ---------------- launch ----------------
extern "C" void kernel_launch(void* const* d_in, const int* in_sizes, int n_in,
                              void* d_out, int out_size)
{
    const float* x      = (const float*)d_in[0];
    const int*   sid    = (const int*)  d_in[1];
    const float* w_time = (const float*)d_in[2];
    const float* b_time = (const float*)d_in[3];
    const float* w_spat = (const float*)d_in[4];
    const float* b_spat = (const float*)d_in[5];
    const float* w2     = (const float*)d_in[6];
    const float* b2     = (const float*)d_in[7];
    const float* w3     = (const float*)d_in[8];
    const float* b3     = (const float*)d_in[9];
    const float* w4     = (const float*)d_in[10];
    const float* b4     = (const float*)d_in[11];
    const float* hW     = (const float*)d_in[12];
    const float* hB     = (const float*)d_in[13];
    float* out = (float*)d_out;

    const int smem1 = (22 * 344 + 25 * 264) * 4;   // 56,672
    const int smem2 = (25 * 336 + 25 * 300) * 4;   // 63,600
    const int smem3 = (10800 + 25 * 600) * 4;      // 103,200
    const int smem4 = (3200 + 50 * 201 + 3) * 4;   // 53,012
    cudaFuncSetAttribute(stage1_k, cudaFuncAttributeMaxDynamicSharedMemorySize, smem1);
    cudaFuncSetAttribute(stage2_k, cudaFuncAttributeMaxDynamicSharedMemorySize, smem2);
    cudaFuncSetAttribute(stage3_k, cudaFuncAttributeMaxDynamicSharedMemorySize, smem3);
    cudaFuncSetAttribute(stage4_k, cudaFuncAttributeMaxDynamicSharedMemorySize, smem4);

    precompute_k<<<1, 256>>>(w_time, b_time, w_spat, b_spat);
    stage1_k<<<dim3(B_, 3), 224, smem1>>>(x);
    stage2_k<<<dim3(B_, 2), 224, smem2>>>(w2, b2);
    stage3_k<<<dim3(128, 4), 256, smem3>>>(w3, b3);
    stage4_k<<<B_, 224, smem4>>>(w4, b4);
    head_k<<<B_, 128>>>(sid, hW, hB, out);
}

// round 5
// speedup vs baseline: 1.1002x; 1.1002x over previous
#include <cuda_runtime.h>
#include <cuda_bf16.h>
#include <math.h>
#include <stdint.h>

#define B_ 256

// ---------------- device scratch ----------------
__device__ float g_Weff[25 * 220];
__device__ float g_beff[25];
__device__ float g_y1[B_ * 25 * 330];
__device__ float g_y2[B_ * 50 * 107];
__device__ float g_y3[B_ * 100 * 32];
__device__ float g_feat[B_ * 1400];

__device__ __forceinline__ float elu1(float x) { return x > 0.f ? x : expm1f(x); }

__device__ __forceinline__ uint32_t smem_u32(const void* p) {
    uint32_t a;
    asm("{ .reg .u64 t; cvta.to.shared.u64 t, %1; cvt.u32.u64 %0, t; }" : "=r"(a) : "l"(p));
    return a;
}
__device__ __forceinline__ void ldsm4(uint32_t* r, uint32_t addr) {
    asm volatile("ldmatrix.sync.aligned.m8n8.x4.shared.b16 {%0,%1,%2,%3}, [%4];"
                 : "=r"(r[0]), "=r"(r[1]), "=r"(r[2]), "=r"(r[3]) : "r"(addr));
}
__device__ __forceinline__ void mma16816(float* d, const uint32_t* a, const uint32_t* b) {
    asm volatile("mma.sync.aligned.m16n8k16.row.col.f32.bf16.bf16.f32 "
                 "{%0,%1,%2,%3}, {%4,%5,%6,%7}, {%8,%9}, {%0,%1,%2,%3};"
                 : "+f"(d[0]), "+f"(d[1]), "+f"(d[2]), "+f"(d[3])
                 : "r"(a[0]), "r"(a[1]), "r"(a[2]), "r"(a[3]), "r"(b[0]), "r"(b[1]));
}

// ---------------- kernel 0: fold conv_time into conv_spat ----------------
__global__ void precompute_k(const float* __restrict__ w_time, const float* __restrict__ b_time,
                             const float* __restrict__ w_spat, const float* __restrict__ b_spat)
{
    for (int idx = threadIdx.x; idx < 25 * 220; idx += blockDim.x) {
        int p = idx / 220, rem = idx % 220, c = rem / 10, k = rem % 10;
        float s = 0.f;
        #pragma unroll
        for (int o = 0; o < 25; o++)
            s = fmaf(w_spat[p * 550 + o * 22 + c], w_time[o * 10 + k], s);
        g_Weff[idx] = s;
    }
    if (threadIdx.x < 25) {
        int p = threadIdx.x;
        float s = b_spat[p];
        for (int o = 0; o < 25; o++) {
            float w = 0.f;
            for (int c = 0; c < 22; c++) w += w_spat[p * 550 + o * 22 + c];
            s = fmaf(b_time[o], w, s);
        }
        g_beff[p] = s;
    }
}

// ---------------- scalar conv body (round-2 proven) ----------------
template<int P, int C, int XS, int WS>
__device__ __forceinline__ void conv_acc(const float* __restrict__ xs,
                                         const float* __restrict__ ws,
                                         float* __restrict__ acc)
{
    #pragma unroll
    for (int i = 0; i < P * 3; i++) acc[i] = 0.f;
    #pragma unroll 1
    for (int c = 0; c < C; c++) {
        float xr[12];
        #pragma unroll
        for (int i = 0; i < 12; i++) xr[i] = xs[c * XS + i];
        #pragma unroll
        for (int p = 0; p < P; p++) {
            const float* wp = ws + p * WS + c * 12;
            float4 w0 = *reinterpret_cast<const float4*>(wp);
            float4 w1 = *reinterpret_cast<const float4*>(wp + 4);
            float2 w2 = *reinterpret_cast<const float2*>(wp + 8);
            float wk[10] = {w0.x, w0.y, w0.z, w0.w, w1.x, w1.y, w1.z, w1.w, w2.x, w2.y};
            #pragma unroll
            for (int k = 0; k < 10; k++) {
                acc[p * 3 + 0] = fmaf(wk[k], xr[k + 0], acc[p * 3 + 0]);
                acc[p * 3 + 1] = fmaf(wk[k], xr[k + 1], acc[p * 3 + 1]);
                acc[p * 3 + 2] = fmaf(wk[k], xr[k + 2], acc[p * 3 + 2]);
            }
        }
    }
}

// ---------------- stage 1: x[256,22,1000] -> y1[256,25,330] ----------------
__global__ __launch_bounds__(352, 2) void stage1_k(const float* __restrict__ x)
{
    extern __shared__ float sm[];
    float* xs = sm;                // [22][504]
    float* ws = sm + 22 * 504;     // [25][264]
    __shared__ float bs[25];
    const int b = blockIdx.x, half = blockIdx.y;
    const int xoff = half * 495;
    const float* xb = x + b * 22000;
    for (int i = threadIdx.x; i < 22 * 504; i += 352) {
        int c = i / 504, t = i - c * 504;
        xs[i] = xb[c * 1000 + xoff + t];
    }
    for (int i = threadIdx.x; i < 5500; i += 352) {
        int p = i / 220, r = i - p * 220;
        int c = r / 10, k = r - c * 10;
        ws[p * 264 + c * 12 + k] = g_Weff[i];
    }
    if (threadIdx.x < 25) bs[threadIdx.x] = g_beff[threadIdx.x];
    __syncthreads();

    const int tpL = threadIdx.x % 176;
    const int pg  = threadIdx.x / 176;
    if (tpL >= 165) return;
    const float* xp = xs + 3 * tpL;
    const int tp = half * 165 + tpL;

    if (pg == 0) {
        float acc[39];
        conv_acc<13, 22, 504, 264>(xp, ws, acc);
        #pragma unroll
        for (int p = 0; p < 13; p++) {
            float m = fmaxf(acc[p * 3], fmaxf(acc[p * 3 + 1], acc[p * 3 + 2])) + bs[p];
            g_y1[b * 8250 + p * 330 + tp] = elu1(m);
        }
    } else {
        float acc[36];
        conv_acc<12, 22, 504, 264>(xp, ws + 13 * 264, acc);
        #pragma unroll
        for (int p = 0; p < 12; p++) {
            float m = fmaxf(acc[p * 3], fmaxf(acc[p * 3 + 1], acc[p * 3 + 2])) + bs[13 + p];
            g_y1[b * 8250 + (13 + p) * 330 + tp] = elu1(m);
        }
    }
}

// ---------------- stage 2: y1 -> y2[256,50,107] ----------------
__global__ __launch_bounds__(448, 2) void stage2_k(const float* __restrict__ w2,
                                                   const float* __restrict__ b2)
{
    extern __shared__ float sm[];
    float* xs = sm;            // [25][330] (+2 pad)
    float* ws = sm + 8252;     // [25][300]
    const int b = blockIdx.x, half = blockIdx.y;
    const float* xb = g_y1 + b * 8250;
    for (int i = threadIdx.x; i < 8250; i += 448) xs[i] = xb[i];
    for (int i = threadIdx.x; i < 6250; i += 448) {
        int p = i / 250, r = i - p * 250;
        int c = r / 10, k = r - c * 10;
        ws[p * 300 + c * 12 + k] = w2[(half * 25 + p) * 250 + r];
    }
    __syncthreads();

    const int tp = threadIdx.x % 112;
    const int pg = threadIdx.x / 112;
    if (tp >= 107) return;
    const float* xp = xs + 3 * tp;
    const int P0 = (pg == 0) ? 0 : 7 + 6 * (pg - 1);
    const int P  = (pg == 0) ? 7 : 6;

    float acc[21];
    if (pg == 0) conv_acc<7, 25, 330, 300>(xp, ws, acc);
    else         conv_acc<6, 25, 330, 300>(xp, ws + P0 * 300, acc);

    for (int p = 0; p < P; p++) {
        int och = half * 25 + P0 + p;
        float m = fmaxf(acc[p * 3], fmaxf(acc[p * 3 + 1], acc[p * 3 + 2])) + __ldg(&b2[och]);
        g_y2[b * 5350 + och * 107 + tp] = elu1(m);
    }
}

// ---------------- stage 3 (TENSOR via mma.sync): y2 -> y3 ----------------
// per CTA (2 samples): D[128][192] = A[128][512] * B[192][512]^T
// A = w3 (100->128 rows, 500->512 K zero-padded), B = im2col of y2.
// bf16 3-split: D += Ah*Bh + Al*Bh + Ah*Bl. K-chunks of 128 (pad rows to 136 bf16).
#define S3_KP 136
#define S3_AH 0
#define S3_AL (128 * S3_KP * 2)            // 34816
#define S3_BH (2 * 128 * S3_KP * 2)        // 69632
#define S3_BL (S3_BH + 192 * S3_KP * 2)    // 121856
#define S3_SMEM (S3_BL + 192 * S3_KP * 2)  // 174080

__global__ __launch_bounds__(256, 1) void stage3_k(const float* __restrict__ w3,
                                                   const float* __restrict__ b3)
{
    extern __shared__ char smc[];
    const uint32_t sb = smem_u32(smc);
    const int tid = threadIdx.x, wid = tid >> 5, lane = tid & 31;
    const int s0 = blockIdx.x * 2;

    float d[24][4];
    #pragma unroll
    for (int i = 0; i < 24; i++)
        #pragma unroll
        for (int j = 0; j < 4; j++) d[i][j] = 0.f;

    // ldmatrix lane address bases
    const uint32_t warp_m = wid * 16;
    const uint32_t aOff = ((warp_m + ((lane >> 3) & 1) * 8 + (lane & 7)) * S3_KP + (lane >> 4) * 8) * 2;
    const uint32_t bOff = (((lane >> 4) * 8 + (lane & 7)) * S3_KP + ((lane >> 3) & 1) * 8) * 2;
    const uint32_t aH = sb + S3_AH + aOff, aL = sb + S3_AL + aOff;
    const uint32_t bH = sb + S3_BH + bOff, bL = sb + S3_BL + bOff;

    for (int ch = 0; ch < 4; ch++) {
        const int kb = ch * 128;
        __syncthreads();
        // fill A chunk [128][128]
        for (int i = tid; i < 16384; i += 256) {
            int row = i >> 7, k = i & 127, gk = kb + k;
            float v = (row < 100 && gk < 500) ? __ldg(&w3[row * 500 + gk]) : 0.f;
            __nv_bfloat16 h = __float2bfloat16(v);
            __nv_bfloat16 l = __float2bfloat16(v - __bfloat162float(h));
            int off = (row * S3_KP + k) * 2;
            *reinterpret_cast<__nv_bfloat16*>(smc + S3_AH + off) = h;
            *reinterpret_cast<__nv_bfloat16*>(smc + S3_AL + off) = l;
        }
        // fill B chunk [192][128] (im2col)
        for (int i = tid; i < 24576; i += 256) {
            int n = i >> 7, k = i & 127, gk = kb + k;
            float v = 0.f;
            if (gk < 500) {
                int c = gk / 10, kk = gk - c * 10;
                int s = (n >= 96) ? 1 : 0;
                int j = n - 96 * s;
                v = g_y2[(s0 + s) * 5350 + c * 107 + j + kk];
            }
            __nv_bfloat16 h = __float2bfloat16(v);
            __nv_bfloat16 l = __float2bfloat16(v - __bfloat162float(h));
            int off = (n * S3_KP + k) * 2;
            *reinterpret_cast<__nv_bfloat16*>(smc + S3_BH + off) = h;
            *reinterpret_cast<__nv_bfloat16*>(smc + S3_BL + off) = l;
        }
        __syncthreads();

        #pragma unroll
        for (int t = 0; t < 8; t++) {
            uint32_t ah[4], al[4];
            ldsm4(ah, aH + t * 32);
            ldsm4(al, aL + t * 32);
            #pragma unroll
            for (int q = 0; q < 12; q++) {
                uint32_t bh[4], bl[4];
                ldsm4(bh, bH + q * 16 * S3_KP * 2 + t * 32);
                ldsm4(bl, bL + q * 16 * S3_KP * 2 + t * 32);
                mma16816(d[2 * q],     ah, bh);
                mma16816(d[2 * q],     al, bh);
                mma16816(d[2 * q],     ah, bl);
                mma16816(d[2 * q + 1], ah, bh + 2);
                mma16816(d[2 * q + 1], al, bh + 2);
                mma16816(d[2 * q + 1], ah, bl + 2);
            }
        }
    }

    // epilogue: accums -> smem f32 [128][200], then pool + ELU + store
    __syncthreads();
    float* Dsm = reinterpret_cast<float*>(smc);
    {
        const int r0 = wid * 16 + (lane >> 2);
        const int cb = (lane & 3) * 2;
        #pragma unroll
        for (int nt = 0; nt < 24; nt++) {
            int n = nt * 8 + cb;
            Dsm[r0 * 200 + n]           = d[nt][0];
            Dsm[r0 * 200 + n + 1]       = d[nt][1];
            Dsm[(r0 + 8) * 200 + n]     = d[nt][2];
            Dsm[(r0 + 8) * 200 + n + 1] = d[nt][3];
        }
    }
    __syncthreads();
    for (int i = tid; i < 6400; i += 256) {
        int o = i >> 6, r = i & 63, s = r >> 5, t = r & 31;
        int n = s * 96 + t * 3;
        float v = fmaxf(Dsm[o * 200 + n], fmaxf(Dsm[o * 200 + n + 1], Dsm[o * 200 + n + 2]))
                  + __ldg(&b3[o]);
        g_y3[(s0 + s) * 3200 + o * 32 + t] = elu1(v);
    }
}

// ---------------- stage 4: y3 -> feat[256,1400] ----------------
__global__ __launch_bounds__(224, 3) void stage4_k(const float* __restrict__ w4,
                                                   const float* __restrict__ b4)
{
    extern __shared__ float sm[];
    float* xs = sm;             // [100][32]
    float* wc = sm + 3200;      // [50][201]
    const int b = blockIdx.x;
    const int o = threadIdx.x;
    for (int i = threadIdx.x; i < 3200; i += 224) xs[i] = g_y3[b * 3200 + i];

    float acc[21];
    #pragma unroll
    for (int i = 0; i < 21; i++) acc[i] = 0.f;

    for (int c0 = 0; c0 < 100; c0 += 5) {
        __syncthreads();
        const float2* wg = reinterpret_cast<const float2*>(w4 + c0 * 10);
        for (int i = threadIdx.x; i < 5000; i += 224) {
            int oo = i / 25, r2 = i - oo * 25;
            float2 v = __ldg(&wg[oo * 500 + r2]);
            wc[(2 * r2) * 201 + oo]     = v.x;
            wc[(2 * r2 + 1) * 201 + oo] = v.y;
        }
        __syncthreads();
        if (o < 200) {
            #pragma unroll
            for (int c = 0; c < 5; c++) {
                float xr[32];
                const float4* xp = reinterpret_cast<const float4*>(xs + (c0 + c) * 32);
                #pragma unroll
                for (int q = 0; q < 8; q++) {
                    float4 v = xp[q];
                    xr[q * 4 + 0] = v.x; xr[q * 4 + 1] = v.y;
                    xr[q * 4 + 2] = v.z; xr[q * 4 + 3] = v.w;
                }
                #pragma unroll
                for (int k = 0; k < 10; k++) {
                    float wv = wc[(c * 10 + k) * 201 + o];
                    #pragma unroll
                    for (int j = 0; j < 21; j++)
                        acc[j] = fmaf(wv, xr[j + k], acc[j]);
                }
            }
        }
    }

    if (o < 200) {
        float bo = __ldg(&b4[o]);
        #pragma unroll
        for (int t = 0; t < 7; t++) {
            float m = fmaxf(acc[3 * t], fmaxf(acc[3 * t + 1], acc[3 * t + 2])) + bo;
            g_feat[b * 1400 + o * 7 + t] = elu1(m);
        }
    }
}

// ---------------- head ----------------
__global__ void head_k(const int* __restrict__ sid, const float* __restrict__ hW,
                       const float* __restrict__ hB, float* __restrict__ out)
{
    const int b = blockIdx.x;
    const int s = sid[b];
    const float* f = g_feat + b * 1400;
    const float* W = hW + s * (4 * 1400);
    float acc[4] = {0.f, 0.f, 0.f, 0.f};
    for (int i = threadIdx.x; i < 1400; i += blockDim.x) {
        float fv = f[i];
        #pragma unroll
        for (int o = 0; o < 4; o++) acc[o] = fmaf(fv, __ldg(&W[o * 1400 + i]), acc[o]);
    }
    #pragma unroll
    for (int off = 16; off > 0; off >>= 1) {
        #pragma unroll
        for (int o = 0; o < 4; o++) acc[o] += __shfl_down_sync(0xFFFFFFFFu, acc[o], off);
    }
    __shared__ float red[4][4];
    const int w = threadIdx.x >> 5, l = threadIdx.x & 31;
    if (l == 0) {
        #pragma unroll
        for (int o = 0; o < 4; o++) red[o][w] = acc[o];
    }
    __syncthreads();
    if (threadIdx.x < 4) {
        int o = threadIdx.x;
        out[b * 4 + o] = red[o][0] + red[o][1] + red[o][2] + red[o][3] + __ldg(&hB[s * 4 + o]);
    }
}

// ---------------- launch ----------------
extern "C" void kernel_launch(void* const* d_in, const int* in_sizes, int n_in,
                              void* d_out, int out_size)
{
    const float* x      = (const float*)d_in[0];
    const int*   sid    = (const int*)  d_in[1];
    const float* w_time = (const float*)d_in[2];
    const float* b_time = (const float*)d_in[3];
    const float* w_spat = (const float*)d_in[4];
    const float* b_spat = (const float*)d_in[5];
    const float* w2     = (const float*)d_in[6];
    const float* b2     = (const float*)d_in[7];
    const float* w3     = (const float*)d_in[8];
    const float* b3     = (const float*)d_in[9];
    const float* w4     = (const float*)d_in[10];
    const float* b4     = (const float*)d_in[11];
    const float* hW     = (const float*)d_in[12];
    const float* hB     = (const float*)d_in[13];
    float* out = (float*)d_out;

    const int smem1 = (22 * 504 + 25 * 264) * 4;     // 70,752
    const int smem2 = (8252 + 25 * 300) * 4;         // 63,008
    const int smem3 = S3_SMEM;                       // 174,080
    const int smem4 = (3200 + 50 * 201 + 3) * 4;     // 53,012
    cudaFuncSetAttribute(stage1_k, cudaFuncAttributeMaxDynamicSharedMemorySize, smem1);
    cudaFuncSetAttribute(stage2_k, cudaFuncAttributeMaxDynamicSharedMemorySize, smem2);
    cudaFuncSetAttribute(stage3_k, cudaFuncAttributeMaxDynamicSharedMemorySize, smem3);
    cudaFuncSetAttribute(stage4_k, cudaFuncAttributeMaxDynamicSharedMemorySize, smem4);

    precompute_k<<<1, 256>>>(w_time, b_time, w_spat, b_spat);
    stage1_k<<<dim3(B_, 2), 352, smem1>>>(x);
    stage2_k<<<dim3(B_, 2), 448, smem2>>>(w2, b2);
    stage3_k<<<128, 256, smem3>>>(w3, b3);
    stage4_k<<<B_, 224, smem4>>>(w4, b4);
    head_k<<<B_, 128>>>(sid, hW, hB, out);
}

// round 6
// speedup vs baseline: 1.1638x; 1.0578x over previous
#include <cuda_runtime.h>
#include <cuda_bf16.h>
#include <math.h>
#include <stdint.h>

#define B_ 256

// ---------------- device scratch ----------------
__device__ float g_Weff[25 * 220];
__device__ float g_beff[25];
__device__ float g_y1[B_ * 25 * 330];
__device__ uint32_t g_y2p[B_ * 50 * 107];            // packed bf16 h | l<<16
__device__ float g_y3[B_ * 100 * 32];
__device__ float g_feat[B_ * 1400];
// w3 bf16 split, chunk-image layout: [4 chunks][128 rows][136 k]
__device__ __align__(16) uint16_t g_w3h[4 * 128 * 136];
__device__ __align__(16) uint16_t g_w3l[4 * 128 * 136];

__device__ __forceinline__ float elu1(float x) { return x > 0.f ? x : expm1f(x); }

__device__ __forceinline__ uint32_t smem_u32(const void* p) {
    uint32_t a;
    asm("{ .reg .u64 t; cvta.to.shared.u64 t, %1; cvt.u32.u64 %0, t; }" : "=r"(a) : "l"(p));
    return a;
}
__device__ __forceinline__ void ldsm4(uint32_t* r, uint32_t addr) {
    asm volatile("ldmatrix.sync.aligned.m8n8.x4.shared.b16 {%0,%1,%2,%3}, [%4];"
                 : "=r"(r[0]), "=r"(r[1]), "=r"(r[2]), "=r"(r[3]) : "r"(addr));
}
__device__ __forceinline__ void ldsm4t(uint32_t* r, uint32_t addr) {
    asm volatile("ldmatrix.sync.aligned.m8n8.x4.trans.shared.b16 {%0,%1,%2,%3}, [%4];"
                 : "=r"(r[0]), "=r"(r[1]), "=r"(r[2]), "=r"(r[3]) : "r"(addr));
}
__device__ __forceinline__ void mma16816(float* d, const uint32_t* a, const uint32_t* b) {
    asm volatile("mma.sync.aligned.m16n8k16.row.col.f32.bf16.bf16.f32 "
                 "{%0,%1,%2,%3}, {%4,%5,%6,%7}, {%8,%9}, {%0,%1,%2,%3};"
                 : "+f"(d[0]), "+f"(d[1]), "+f"(d[2]), "+f"(d[3])
                 : "r"(a[0]), "r"(a[1]), "r"(a[2]), "r"(a[3]), "r"(b[0]), "r"(b[1]));
}
__device__ __forceinline__ uint32_t pack_bf16_split(float v) {
    __nv_bfloat16 h = __float2bfloat16(v);
    float hf = __bfloat162float(h);
    __nv_bfloat16 l = __float2bfloat16(v - hf);
    uint16_t hb = reinterpret_cast<uint16_t&>(h);
    uint16_t lb = reinterpret_cast<uint16_t&>(l);
    return (uint32_t)hb | ((uint32_t)lb << 16);
}

// ---------------- kernel 0: fold conv_time into conv_spat ----------------
__global__ void precompute_k(const float* __restrict__ w_time, const float* __restrict__ b_time,
                             const float* __restrict__ w_spat, const float* __restrict__ b_spat)
{
    for (int idx = threadIdx.x; idx < 25 * 220; idx += blockDim.x) {
        int p = idx / 220, rem = idx % 220, c = rem / 10, k = rem % 10;
        float s = 0.f;
        #pragma unroll
        for (int o = 0; o < 25; o++)
            s = fmaf(w_spat[p * 550 + o * 22 + c], w_time[o * 10 + k], s);
        g_Weff[idx] = s;
    }
    if (threadIdx.x < 25) {
        int p = threadIdx.x;
        float s = b_spat[p];
        for (int o = 0; o < 25; o++) {
            float w = 0.f;
            for (int c = 0; c < 22; c++) w += w_spat[p * 550 + o * 22 + c];
            s = fmaf(b_time[o], w, s);
        }
        g_beff[p] = s;
    }
}

// ---------------- kernel 0b: w3 bf16 split into chunk-image layout ----------------
__global__ void precompute2_k(const float* __restrict__ w3)   // [100][500]
{
    int idx = blockIdx.x * 256 + threadIdx.x;
    if (idx >= 4 * 128 * 136) return;
    int ch = idx / 17408, r = idx % 17408, row = r / 136, kloc = r % 136;
    int gk = ch * 128 + kloc;
    float v = (kloc < 128 && row < 100 && gk < 500) ? w3[row * 500 + gk] : 0.f;
    uint32_t p = pack_bf16_split(v);
    g_w3h[idx] = (uint16_t)(p & 0xffff);
    g_w3l[idx] = (uint16_t)(p >> 16);
}

// ---------------- scalar conv body (round-2 proven) ----------------
template<int P, int C, int XS, int WS>
__device__ __forceinline__ void conv_acc(const float* __restrict__ xs,
                                         const float* __restrict__ ws,
                                         float* __restrict__ acc)
{
    #pragma unroll
    for (int i = 0; i < P * 3; i++) acc[i] = 0.f;
    #pragma unroll 1
    for (int c = 0; c < C; c++) {
        float xr[12];
        #pragma unroll
        for (int i = 0; i < 12; i++) xr[i] = xs[c * XS + i];
        #pragma unroll
        for (int p = 0; p < P; p++) {
            const float* wp = ws + p * WS + c * 12;
            float4 w0 = *reinterpret_cast<const float4*>(wp);
            float4 w1 = *reinterpret_cast<const float4*>(wp + 4);
            float2 w2 = *reinterpret_cast<const float2*>(wp + 8);
            float wk[10] = {w0.x, w0.y, w0.z, w0.w, w1.x, w1.y, w1.z, w1.w, w2.x, w2.y};
            #pragma unroll
            for (int k = 0; k < 10; k++) {
                acc[p * 3 + 0] = fmaf(wk[k], xr[k + 0], acc[p * 3 + 0]);
                acc[p * 3 + 1] = fmaf(wk[k], xr[k + 1], acc[p * 3 + 1]);
                acc[p * 3 + 2] = fmaf(wk[k], xr[k + 2], acc[p * 3 + 2]);
            }
        }
    }
}

// ---------------- stage 1: x[256,22,1000] -> y1[256,25,330] ----------------
__global__ __launch_bounds__(352, 2) void stage1_k(const float* __restrict__ x)
{
    extern __shared__ float sm[];
    float* xs = sm;                // [22][504]
    float* ws = sm + 22 * 504;     // [25][264]
    __shared__ float bs[25];
    const int b = blockIdx.x, half = blockIdx.y;
    const int xoff = half * 495;
    const float* xb = x + b * 22000;
    for (int i = threadIdx.x; i < 22 * 504; i += 352) {
        int c = i / 504, t = i - c * 504;
        xs[i] = xb[c * 1000 + xoff + t];
    }
    for (int i = threadIdx.x; i < 5500; i += 352) {
        int p = i / 220, r = i - p * 220;
        int c = r / 10, k = r - c * 10;
        ws[p * 264 + c * 12 + k] = g_Weff[i];
    }
    if (threadIdx.x < 25) bs[threadIdx.x] = g_beff[threadIdx.x];
    __syncthreads();

    const int tpL = threadIdx.x % 176;
    const int pg  = threadIdx.x / 176;
    if (tpL >= 165) return;
    const float* xp = xs + 3 * tpL;
    const int tp = half * 165 + tpL;

    if (pg == 0) {
        float acc[39];
        conv_acc<13, 22, 504, 264>(xp, ws, acc);
        #pragma unroll
        for (int p = 0; p < 13; p++) {
            float m = fmaxf(acc[p * 3], fmaxf(acc[p * 3 + 1], acc[p * 3 + 2])) + bs[p];
            g_y1[b * 8250 + p * 330 + tp] = elu1(m);
        }
    } else {
        float acc[36];
        conv_acc<12, 22, 504, 264>(xp, ws + 13 * 264, acc);
        #pragma unroll
        for (int p = 0; p < 12; p++) {
            float m = fmaxf(acc[p * 3], fmaxf(acc[p * 3 + 1], acc[p * 3 + 2])) + bs[13 + p];
            g_y1[b * 8250 + (13 + p) * 330 + tp] = elu1(m);
        }
    }
}

// ---------------- stage 2: y1 -> y2p[256,50,107] (packed bf16 split) ----------------
__global__ __launch_bounds__(448, 2) void stage2_k(const float* __restrict__ w2,
                                                   const float* __restrict__ b2)
{
    extern __shared__ float sm[];
    float* xs = sm;            // [25][330] (+2 pad)
    float* ws = sm + 8252;     // [25][300]
    const int b = blockIdx.x, half = blockIdx.y;
    const float* xb = g_y1 + b * 8250;
    for (int i = threadIdx.x; i < 8250; i += 448) xs[i] = xb[i];
    for (int i = threadIdx.x; i < 6250; i += 448) {
        int p = i / 250, r = i - p * 250;
        int c = r / 10, k = r - c * 10;
        ws[p * 300 + c * 12 + k] = w2[(half * 25 + p) * 250 + r];
    }
    __syncthreads();

    const int tp = threadIdx.x % 112;
    const int pg = threadIdx.x / 112;
    if (tp >= 107) return;
    const float* xp = xs + 3 * tp;
    const int P0 = (pg == 0) ? 0 : 7 + 6 * (pg - 1);
    const int P  = (pg == 0) ? 7 : 6;

    float acc[21];
    if (pg == 0) conv_acc<7, 25, 330, 300>(xp, ws, acc);
    else         conv_acc<6, 25, 330, 300>(xp, ws + P0 * 300, acc);

    for (int p = 0; p < P; p++) {
        int och = half * 25 + P0 + p;
        float m = fmaxf(acc[p * 3], fmaxf(acc[p * 3 + 1], acc[p * 3 + 2])) + __ldg(&b2[och]);
        g_y2p[b * 5350 + och * 107 + tp] = pack_bf16_split(elu1(m));
    }
}

// ---------------- stage 3 (TENSOR, fast fills): y2p -> y3 ----------------
// per CTA (2 samples): D[128][192] = A[128][512] * B[192][512]^T
// A [m][k] stride 136 (from g_w3h/l, plain copy); B [k][n] stride 200, ldmatrix.trans.
#define S3_KP 136
#define S3_NP 200
#define S3_AH 0
#define S3_AL 34816
#define S3_BH 69632
#define S3_BL 120832
#define S3_SMEM 172032

__global__ __launch_bounds__(256, 1) void stage3_k(const float* __restrict__ b3)
{
    extern __shared__ char smc[];
    const uint32_t sb = smem_u32(smc);
    const int tid = threadIdx.x, wid = tid >> 5, lane = tid & 31;
    const int s0 = blockIdx.x * 2;

    float d[24][4];
    #pragma unroll
    for (int i = 0; i < 24; i++)
        #pragma unroll
        for (int j = 0; j < 4; j++) d[i][j] = 0.f;

    // ldmatrix lane bases
    const uint32_t aOff = ((wid * 16 + ((lane >> 3) & 1) * 8 + (lane & 7)) * S3_KP + (lane >> 4) * 8) * 2;
    const uint32_t bOff = ((((lane >> 3) & 1) * 8 + (lane & 7)) * S3_NP + (lane >> 4) * 8) * 2;
    const uint32_t aH = sb + S3_AH + aOff, aL = sb + S3_AL + aOff;
    const uint32_t bHb = sb + S3_BH + bOff, bLb = sb + S3_BL + bOff;

    // B-fill thread mapping (fixed per chunk): row kloc, sample segment seg
    const int kloc = tid >> 1, seg = tid & 1;
    uint16_t* bhRow = reinterpret_cast<uint16_t*>(smc + S3_BH) + kloc * S3_NP + seg * 96;
    uint16_t* blRow = reinterpret_cast<uint16_t*>(smc + S3_BL) + kloc * S3_NP + seg * 96;

    for (int ch = 0; ch < 4; ch++) {
        __syncthreads();
        // A: straight copy of precomputed chunk image (34,816 B per buffer)
        {
            const float4* srcH = reinterpret_cast<const float4*>(g_w3h + ch * 17408);
            const float4* srcL = reinterpret_cast<const float4*>(g_w3l + ch * 17408);
            float4* dstH = reinterpret_cast<float4*>(smc + S3_AH);
            float4* dstL = reinterpret_cast<float4*>(smc + S3_AL);
            #pragma unroll 1
            for (int i = tid; i < 2176; i += 256) { dstH[i] = srcH[i]; dstL[i] = srcL[i]; }
        }
        // B: gather packed y2 into [k][n] rows
        {
            const int gk = ch * 128 + kloc;
            if (gk < 500) {
                const int c = gk / 10, kk = gk - c * 10;
                const uint32_t* src = g_y2p + (s0 + seg) * 5350 + c * 107 + kk;
                #pragma unroll 8
                for (int j = 0; j < 96; j++) {
                    uint32_t p = __ldg(&src[j]);
                    bhRow[j] = (uint16_t)(p & 0xffff);
                    blRow[j] = (uint16_t)(p >> 16);
                }
            } else {
                #pragma unroll 8
                for (int j = 0; j < 96; j++) { bhRow[j] = 0; blRow[j] = 0; }
            }
        }
        __syncthreads();

        #pragma unroll
        for (int t = 0; t < 8; t++) {
            uint32_t ah[4], al[4];
            ldsm4(ah, aH + t * 32);
            ldsm4(al, aL + t * 32);
            const uint32_t bt = (uint32_t)t * (16 * S3_NP * 2);
            #pragma unroll
            for (int q = 0; q < 12; q++) {
                uint32_t bh[4], bl[4];
                ldsm4t(bh, bHb + bt + q * 32);
                ldsm4t(bl, bLb + bt + q * 32);
                mma16816(d[2 * q],     ah, bh);
                mma16816(d[2 * q],     al, bh);
                mma16816(d[2 * q],     ah, bl);
                mma16816(d[2 * q + 1], ah, bh + 2);
                mma16816(d[2 * q + 1], al, bh + 2);
                mma16816(d[2 * q + 1], ah, bl + 2);
            }
        }
    }

    // epilogue: accums -> smem f32 [128][200], pool + ELU + store
    __syncthreads();
    float* Dsm = reinterpret_cast<float*>(smc);
    {
        const int r0 = wid * 16 + (lane >> 2);
        const int cb = (lane & 3) * 2;
        #pragma unroll
        for (int nt = 0; nt < 24; nt++) {
            int n = nt * 8 + cb;
            Dsm[r0 * 200 + n]           = d[nt][0];
            Dsm[r0 * 200 + n + 1]       = d[nt][1];
            Dsm[(r0 + 8) * 200 + n]     = d[nt][2];
            Dsm[(r0 + 8) * 200 + n + 1] = d[nt][3];
        }
    }
    __syncthreads();
    for (int i = tid; i < 6400; i += 256) {
        int o = i >> 6, r = i & 63, s = r >> 5, t = r & 31;
        int n = s * 96 + t * 3;
        float v = fmaxf(Dsm[o * 200 + n], fmaxf(Dsm[o * 200 + n + 1], Dsm[o * 200 + n + 2]))
                  + __ldg(&b3[o]);
        g_y3[(s0 + s) * 3200 + o * 32 + t] = elu1(v);
    }
}

// ---------------- stage 4: y3 -> feat[256,1400] ----------------
__global__ __launch_bounds__(224, 3) void stage4_k(const float* __restrict__ w4,
                                                   const float* __restrict__ b4)
{
    extern __shared__ float sm[];
    float* xs = sm;             // [100][32]
    float* wc = sm + 3200;      // [50][201]
    const int b = blockIdx.x;
    const int o = threadIdx.x;
    for (int i = threadIdx.x; i < 3200; i += 224) xs[i] = g_y3[b * 3200 + i];

    float acc[21];
    #pragma unroll
    for (int i = 0; i < 21; i++) acc[i] = 0.f;

    for (int c0 = 0; c0 < 100; c0 += 5) {
        __syncthreads();
        const float2* wg = reinterpret_cast<const float2*>(w4 + c0 * 10);
        for (int i = threadIdx.x; i < 5000; i += 224) {
            int oo = i / 25, r2 = i - oo * 25;
            float2 v = __ldg(&wg[oo * 500 + r2]);
            wc[(2 * r2) * 201 + oo]     = v.x;
            wc[(2 * r2 + 1) * 201 + oo] = v.y;
        }
        __syncthreads();
        if (o < 200) {
            #pragma unroll
            for (int c = 0; c < 5; c++) {
                float xr[32];
                const float4* xp = reinterpret_cast<const float4*>(xs + (c0 + c) * 32);
                #pragma unroll
                for (int q = 0; q < 8; q++) {
                    float4 v = xp[q];
                    xr[q * 4 + 0] = v.x; xr[q * 4 + 1] = v.y;
                    xr[q * 4 + 2] = v.z; xr[q * 4 + 3] = v.w;
                }
                #pragma unroll
                for (int k = 0; k < 10; k++) {
                    float wv = wc[(c * 10 + k) * 201 + o];
                    #pragma unroll
                    for (int j = 0; j < 21; j++)
                        acc[j] = fmaf(wv, xr[j + k], acc[j]);
                }
            }
        }
    }

    if (o < 200) {
        float bo = __ldg(&b4[o]);
        #pragma unroll
        for (int t = 0; t < 7; t++) {
            float m = fmaxf(acc[3 * t], fmaxf(acc[3 * t + 1], acc[3 * t + 2])) + bo;
            g_feat[b * 1400 + o * 7 + t] = elu1(m);
        }
    }
}

// ---------------- head ----------------
__global__ void head_k(const int* __restrict__ sid, const float* __restrict__ hW,
                       const float* __restrict__ hB, float* __restrict__ out)
{
    const int b = blockIdx.x;
    const int s = sid[b];
    const float* f = g_feat + b * 1400;
    const float* W = hW + s * (4 * 1400);
    float acc[4] = {0.f, 0.f, 0.f, 0.f};
    for (int i = threadIdx.x; i < 1400; i += blockDim.x) {
        float fv = f[i];
        #pragma unroll
        for (int o = 0; o < 4; o++) acc[o] = fmaf(fv, __ldg(&W[o * 1400 + i]), acc[o]);
    }
    #pragma unroll
    for (int off = 16; off > 0; off >>= 1) {
        #pragma unroll
        for (int o = 0; o < 4; o++) acc[o] += __shfl_down_sync(0xFFFFFFFFu, acc[o], off);
    }
    __shared__ float red[4][4];
    const int w = threadIdx.x >> 5, l = threadIdx.x & 31;
    if (l == 0) {
        #pragma unroll
        for (int o = 0; o < 4; o++) red[o][w] = acc[o];
    }
    __syncthreads();
    if (threadIdx.x < 4) {
        int o = threadIdx.x;
        out[b * 4 + o] = red[o][0] + red[o][1] + red[o][2] + red[o][3] + __ldg(&hB[s * 4 + o]);
    }
}

// ---------------- launch ----------------
extern "C" void kernel_launch(void* const* d_in, const int* in_sizes, int n_in,
                              void* d_out, int out_size)
{
    const float* x      = (const float*)d_in[0];
    const int*   sid    = (const int*)  d_in[1];
    const float* w_time = (const float*)d_in[2];
    const float* b_time = (const float*)d_in[3];
    const float* w_spat = (const float*)d_in[4];
    const float* b_spat = (const float*)d_in[5];
    const float* w2     = (const float*)d_in[6];
    const float* b2     = (const float*)d_in[7];
    const float* w3     = (const float*)d_in[8];
    const float* b3     = (const float*)d_in[9];
    const float* w4     = (const float*)d_in[10];
    const float* b4     = (const float*)d_in[11];
    const float* hW     = (const float*)d_in[12];
    const float* hB     = (const float*)d_in[13];
    float* out = (float*)d_out;

    const int smem1 = (22 * 504 + 25 * 264) * 4;     // 70,752
    const int smem2 = (8252 + 25 * 300) * 4;         // 63,008
    const int smem3 = S3_SMEM;                       // 172,032
    const int smem4 = (3200 + 50 * 201 + 3) * 4;     // 53,012
    cudaFuncSetAttribute(stage1_k, cudaFuncAttributeMaxDynamicSharedMemorySize, smem1);
    cudaFuncSetAttribute(stage2_k, cudaFuncAttributeMaxDynamicSharedMemorySize, smem2);
    cudaFuncSetAttribute(stage3_k, cudaFuncAttributeMaxDynamicSharedMemorySize, smem3);
    cudaFuncSetAttribute(stage4_k, cudaFuncAttributeMaxDynamicSharedMemorySize, smem4);

    precompute_k<<<1, 256>>>(w_time, b_time, w_spat, b_spat);
    precompute2_k<<<(4 * 128 * 136 + 255) / 256, 256>>>(w3);
    stage1_k<<<dim3(B_, 2), 352, smem1>>>(x);
    stage2_k<<<dim3(B_, 2), 448, smem2>>>(w2, b2);
    stage3_k<<<128, 256, smem3>>>(b3);
    stage4_k<<<B_, 224, smem4>>>(w4, b4);
    head_k<<<B_, 128>>>(sid, hW, hB, out);
}